// round 4
// baseline (speedup 1.0000x reference)
#include <cuda_runtime.h>
#include <cstdint>

// Problem constants
constexpr int B_ = 16, C_ = 128, H_ = 72, W_ = 200, K_ = 9;
constexpr int CS = H_ * W_;               // channel stride (same in transposed layout)
constexpr size_t BS = (size_t)C_ * CS;    // batch stride
constexpr size_t TOTAL = (size_t)B_ * BS;

constexpr int TCO = 16;                   // c_out channels per CTA
constexpr int NCTA = C_ / TCO;            // 8 CTAs per cluster (one batch image)
constexpr int WSZ = C_ * K_;              // 1152 weights per c_out
constexpr int WSTR = WSZ + 1;             // 1153: odd stride -> co's hit distinct banks

// Scratch for the (B,C,W,H)-transposed layout
__device__ float g_tbuf[TOTAL];

__device__ __forceinline__ uint32_t smem_u32(const void* p) {
    uint32_t a;
    asm("{ .reg .u64 t; cvta.to.shared.u64 t, %1; cvt.u32.u64 %0, t; }" : "=r"(a) : "l"(p));
    return a;
}
__device__ __forceinline__ uint32_t mapa_rank(uint32_t addr, int rank) {
    uint32_t r;
    asm("mapa.shared::cluster.u32 %0, %1, %2;" : "=r"(r) : "r"(addr), "r"(rank));
    return r;
}
__device__ __forceinline__ void st_cluster_f32(uint32_t addr, float v) {
    asm volatile("st.shared::cluster.f32 [%0], %1;" :: "r"(addr), "f"(v) : "memory");
}
__device__ __forceinline__ void cluster_barrier() {
    asm volatile("barrier.cluster.arrive.aligned;" ::: "memory");
    asm volatile("barrier.cluster.wait.aligned;" ::: "memory");
}

// Persistent pass kernel: forward scan with wA, then backward scan with wB.
// Cluster of 8 CTAs = one batch image; CTA 'slice' owns c_out [slice*16, slice*16+16).
// prev row lives in smem (p_s), exchanged between CTAs via DSMEM pushes each step.
// L = conv-axis length (contiguous), JT = j's per thread, NT = threads.
template <int L, int JT, int NT>
__global__ void __launch_bounds__(NT, 1) __cluster_dims__(NCTA, 1, 1)
pass_kernel(float* __restrict__ base, const float* __restrict__ wA,
            const float* __restrict__ wB, int nrows) {
    constexpr int PSTR = L + 8;           // prev-row stride (4-halo each side)

    extern __shared__ float sm[];
    float* w_s = sm;                      // [16][WSTR]  w_s[co][ci*9+k]
    float* p_s = sm + TCO * WSTR;         // [128][PSTR] full prev row, all channels

    const int t = threadIdx.x;
    const int slice = blockIdx.x;         // 0..7
    const int b = blockIdx.y;
    const int co = t & 15;                // local c_out (1 per thread)
    const int jg = t >> 4;                // j group
    const int j0 = jg * JT;
    const int gco = slice * TCO + co;     // global channel this thread produces
    float* __restrict__ bb = base + (size_t)b * BS;

    // local & remote smem addresses for the DSMEM push of this thread's outputs
    const uint32_t my_ps = smem_u32(p_s) + (uint32_t)(gco * PSTR + 4 + j0) * 4u;
    uint32_t peer[NCTA];
    #pragma unroll
    for (int r = 0; r < NCTA; ++r) peer[r] = mapa_rank(my_ps, r);

    // zero the halos once (interior rewritten every step)
    for (int i = t; i < C_; i += NT) {
        #pragma unroll
        for (int kk = 0; kk < 4; ++kk) {
            p_s[i * PSTR + kk] = 0.f;
            p_s[i * PSTR + 4 + L + kk] = 0.f;
        }
    }

    for (int dir = 0; dir < 2; ++dir) {
        const float* __restrict__ w = dir ? wB : wA;

        // stage this CTA's weight slice (16 x 1152) once per direction
        __syncthreads();
        for (int i = t; i < TCO * WSZ; i += NT) {
            int c = i / WSZ, r = i % WSZ;
            w_s[c * WSTR + r] = w[(size_t)(slice * TCO + c) * WSZ + r];
        }
        // initial prev row (all 128 channels) from global
        {
            const int r0 = dir ? (nrows - 1) : 0;
            const float* __restrict__ irow = bb + (size_t)r0 * L;
            for (int i = t; i < C_ * L; i += NT) {
                int ci = i / L, x = i % L;
                p_s[ci * PSTR + 4 + x] = irow[(size_t)ci * CS + x];
            }
        }
        __syncthreads();

        const float* __restrict__ wp = w_s + co * WSTR;

        for (int s = 1; s < nrows; ++s) {
            const int cur = dir ? (nrows - 1 - s) : s;
            float* __restrict__ crow = bb + (size_t)cur * L;

            // ---- main FMA loop: acc[n] = sum_{ci,k} w[ci*9+k] * prev[ci][j0+n+k-4]
            float acc[JT];
            #pragma unroll
            for (int n = 0; n < JT; ++n) acc[n] = 0.f;

            const float* pr = p_s + j0;   // +4 halo cancels the -4 of k offset
            #pragma unroll 2
            for (int ci = 0; ci < C_; ++ci) {
                float pw[JT + 8];
                #pragma unroll
                for (int q = 0; q < JT + 8; ++q) pw[q] = pr[q];
                #pragma unroll
                for (int k = 0; k < K_; ++k) {
                    const float wv = wp[ci * K_ + k];
                    #pragma unroll
                    for (int n = 0; n < JT; ++n)
                        acc[n] = fmaf(wv, pw[k + n], acc[n]);
                }
                pr += PSTR;
            }

            // ---- read x (this pass's base value for row cur, own slice only);
            //      issue LDGs now so latency hides under barrier A
            float xv[JT];
            #pragma unroll
            for (int n = 0; n < JT; ++n) xv[n] = crow[(size_t)gco * CS + j0 + n];

            // barrier A: every CTA finished READING p_s for this step
            cluster_barrier();

            // ---- finalize, store to global (fire-and-forget), push to all 8 p_s
            float ov[JT];
            #pragma unroll
            for (int n = 0; n < JT; ++n) {
                ov[n] = xv[n] + fmaxf(acc[n], 0.f);
                crow[(size_t)gco * CS + j0 + n] = ov[n];
            }
            #pragma unroll
            for (int r = 0; r < NCTA; ++r) {
                #pragma unroll
                for (int n = 0; n < JT; ++n)
                    st_cluster_f32(peer[r] + 4u * n, ov[n]);
            }

            // barrier B: pushes visible cluster-wide -> p_s now holds row 'cur'
            cluster_barrier();
        }
    }
}

// Transpose per (b,c) slab: src slab R x Cc (row-major) -> dst slab Cc x R.
__global__ void transpose_kernel(const float* __restrict__ src, float* __restrict__ dst,
                                 int R, int Cc) {
    __shared__ float tile[32][33];
    const size_t slab = blockIdx.z;
    const float* s = src + slab * (size_t)(R * Cc);
    float* d = dst + slab * (size_t)(R * Cc);
    const int c0 = blockIdx.x * 32;
    const int r0 = blockIdx.y * 32;

    #pragma unroll
    for (int i = 0; i < 32; i += 8) {
        int r = r0 + threadIdx.y + i;
        int c = c0 + threadIdx.x;
        if (r < R && c < Cc) tile[threadIdx.y + i][threadIdx.x] = s[(size_t)r * Cc + c];
    }
    __syncthreads();
    #pragma unroll
    for (int i = 0; i < 32; i += 8) {
        int c = c0 + threadIdx.y + i;
        int r = r0 + threadIdx.x;
        if (r < R && c < Cc) d[(size_t)c * R + r] = tile[threadIdx.x][threadIdx.y + i];
    }
}

extern "C" void kernel_launch(void* const* d_in, const int* in_sizes, int n_in,
                              void* d_out, int out_size) {
    const float* x  = (const float*)d_in[0];
    const float* wd = (const float*)d_in[1];
    const float* wu = (const float*)d_in[2];
    const float* wr = (const float*)d_in[3];
    const float* wl = (const float*)d_in[4];
    float* out = (float*)d_out;

    float* tbuf = nullptr;
    cudaGetSymbolAddress((void**)&tbuf, g_tbuf);

    // W pass: 640 threads, 5 j's/thread; H pass: 384 threads, 3 j's/thread
    constexpr int SMEM_W = (TCO * WSTR + C_ * (W_ + 8)) * 4;  // 180,260 B
    constexpr int SMEM_H = (TCO * WSTR + C_ * (H_ + 8)) * 4;  // 114,724 B
    static bool attr_done = false;
    if (!attr_done) {
        cudaFuncSetAttribute((const void*)pass_kernel<W_, 5, 640>,
                             cudaFuncAttributeMaxDynamicSharedMemorySize, SMEM_W);
        cudaFuncSetAttribute((const void*)pass_kernel<H_, 3, 384>,
                             cudaFuncAttributeMaxDynamicSharedMemorySize, SMEM_H);
        attr_done = true;
    }

    // working copy of x (scan runs in-place on out)
    cudaMemcpyAsync(out, x, TOTAL * sizeof(float), cudaMemcpyDeviceToDevice);

    const dim3 grid(NCTA, B_, 1);

    // down + up: conv along W (contiguous), scan over H rows
    pass_kernel<W_, 5, 640><<<grid, 640, SMEM_W>>>(out, wd, wu, H_);

    // transpose (B,C,H,W) -> (B,C,W,H)
    const dim3 tb(32, 8);
    const dim3 tg1((W_ + 31) / 32, (H_ + 31) / 32, B_ * C_);
    transpose_kernel<<<tg1, tb>>>(out, tbuf, H_, W_);

    // right + left: conv along H (now contiguous), scan over W rows
    pass_kernel<H_, 3, 384><<<grid, 384, SMEM_H>>>(tbuf, wr, wl, W_);

    // transpose back
    const dim3 tg2((H_ + 31) / 32, (W_ + 31) / 32, B_ * C_);
    transpose_kernel<<<tg2, tb>>>(tbuf, out, W_, H_);
}

// round 5
// speedup vs baseline: 1.0318x; 1.0318x over previous
#include <cuda_runtime.h>
#include <cstdint>

// Problem constants
constexpr int B_ = 16, C_ = 128, H_ = 72, W_ = 200, K_ = 9;
constexpr int CS = H_ * W_;               // channel stride (same in transposed layout)
constexpr size_t BS = (size_t)C_ * CS;    // batch stride
constexpr size_t TOTAL = (size_t)B_ * BS;

constexpr int TCO = 16;                   // c_out channels per CTA
constexpr int NCTA = C_ / TCO;            // 8 CTAs per cluster (one batch image)
constexpr int WSZ = C_ * K_;              // 1152 weights per c_out
constexpr int WSTR = WSZ + 1;             // 1153: odd stride -> co's hit distinct banks

// Scratch for the (B,C,W,H)-transposed layout
__device__ float g_tbuf[TOTAL];

__device__ __forceinline__ uint32_t smem_u32(const void* p) {
    uint32_t a;
    asm("{ .reg .u64 t; cvta.to.shared.u64 t, %1; cvt.u32.u64 %0, t; }" : "=r"(a) : "l"(p));
    return a;
}
__device__ __forceinline__ uint32_t mapa_rank(uint32_t addr, int rank) {
    uint32_t r;
    asm("mapa.shared::cluster.u32 %0, %1, %2;" : "=r"(r) : "r"(addr), "r"(rank));
    return r;
}
__device__ __forceinline__ void st_cluster_f32(uint32_t addr, float v) {
    asm volatile("st.shared::cluster.f32 [%0], %1;" :: "r"(addr), "f"(v) : "memory");
}
__device__ __forceinline__ void cluster_barrier() {
    asm volatile("barrier.cluster.arrive.aligned;" ::: "memory");
    asm volatile("barrier.cluster.wait.aligned;" ::: "memory");
}

// Persistent pass kernel: forward scan with wA, then backward scan with wB.
// Cluster of 8 CTAs = one batch image; CTA 'slice' owns c_out [slice*16, slice*16+16).
// prev row lives in smem (p_s), exchanged between CTAs via DSMEM pushes each step.
// L = conv-axis length (contiguous), JT = j's per thread, NT = threads.
template <int L, int JT, int NT>
__global__ void __launch_bounds__(NT, 1) __cluster_dims__(NCTA, 1, 1)
pass_kernel(float* __restrict__ base, const float* __restrict__ wA,
            const float* __restrict__ wB, int nrows) {
    constexpr int PSTR = L + 8;           // prev-row stride (4-halo each side)

    extern __shared__ float sm[];
    float* w_s = sm;                      // [16][WSTR]  w_s[co][ci*9+k]
    float* p_s = sm + TCO * WSTR;         // [128][PSTR] full prev row, all channels

    const int t = threadIdx.x;
    const int slice = blockIdx.x;         // 0..7
    const int b = blockIdx.y;
    const int co = t & 15;                // local c_out (1 per thread)
    const int jg = t >> 4;                // j group
    const int j0 = jg * JT;
    const int gco = slice * TCO + co;     // global channel this thread produces
    float* __restrict__ bb = base + (size_t)b * BS;

    // local & remote smem addresses for the DSMEM push of this thread's outputs
    const uint32_t my_ps = smem_u32(p_s) + (uint32_t)(gco * PSTR + 4 + j0) * 4u;
    uint32_t peer[NCTA];
    #pragma unroll
    for (int r = 0; r < NCTA; ++r) peer[r] = mapa_rank(my_ps, r);

    // zero the halos once (interior rewritten every step)
    for (int i = t; i < C_; i += NT) {
        #pragma unroll
        for (int kk = 0; kk < 4; ++kk) {
            p_s[i * PSTR + kk] = 0.f;
            p_s[i * PSTR + 4 + L + kk] = 0.f;
        }
    }

    for (int dir = 0; dir < 2; ++dir) {
        const float* __restrict__ w = dir ? wB : wA;

        // stage this CTA's weight slice (16 x 1152) once per direction
        __syncthreads();
        for (int i = t; i < TCO * WSZ; i += NT) {
            int c = i / WSZ, r = i % WSZ;
            w_s[c * WSTR + r] = w[(size_t)(slice * TCO + c) * WSZ + r];
        }
        // initial prev row (all 128 channels) from global
        {
            const int r0 = dir ? (nrows - 1) : 0;
            const float* __restrict__ irow = bb + (size_t)r0 * L;
            for (int i = t; i < C_ * L; i += NT) {
                int ci = i / L, x = i % L;
                p_s[ci * PSTR + 4 + x] = irow[(size_t)ci * CS + x];
            }
        }
        __syncthreads();

        const float* __restrict__ wp = w_s + co * WSTR;

        for (int s = 1; s < nrows; ++s) {
            const int cur = dir ? (nrows - 1 - s) : s;
            float* __restrict__ crow = bb + (size_t)cur * L;

            // ---- main FMA loop: acc[n] = sum_{ci,k} w[ci*9+k] * prev[ci][j0+n+k-4]
            float acc[JT];
            #pragma unroll
            for (int n = 0; n < JT; ++n) acc[n] = 0.f;

            const float* pr = p_s + j0;   // +4 halo cancels the -4 of k offset
            #pragma unroll 2
            for (int ci = 0; ci < C_; ++ci) {
                float pw[JT + 8];
                #pragma unroll
                for (int q = 0; q < JT + 8; ++q) pw[q] = pr[q];
                #pragma unroll
                for (int k = 0; k < K_; ++k) {
                    const float wv = wp[ci * K_ + k];
                    #pragma unroll
                    for (int n = 0; n < JT; ++n)
                        acc[n] = fmaf(wv, pw[k + n], acc[n]);
                }
                pr += PSTR;
            }

            // ---- read x (this pass's base value for row cur, own slice only);
            //      issue LDGs now so latency hides under barrier A
            float xv[JT];
            #pragma unroll
            for (int n = 0; n < JT; ++n) xv[n] = crow[(size_t)gco * CS + j0 + n];

            // barrier A: every CTA finished READING p_s for this step
            cluster_barrier();

            // ---- finalize, store to global (fire-and-forget), push to all 8 p_s
            float ov[JT];
            #pragma unroll
            for (int n = 0; n < JT; ++n) {
                ov[n] = xv[n] + fmaxf(acc[n], 0.f);
                crow[(size_t)gco * CS + j0 + n] = ov[n];
            }
            #pragma unroll
            for (int r = 0; r < NCTA; ++r) {
                #pragma unroll
                for (int n = 0; n < JT; ++n)
                    st_cluster_f32(peer[r] + 4u * n, ov[n]);
            }

            // barrier B: pushes visible cluster-wide -> p_s now holds row 'cur'
            cluster_barrier();
        }
    }
}

// Transpose per (b,c) slab: src slab R x Cc (row-major) -> dst slab Cc x R.
__global__ void transpose_kernel(const float* __restrict__ src, float* __restrict__ dst,
                                 int R, int Cc) {
    __shared__ float tile[32][33];
    const size_t slab = blockIdx.z;
    const float* s = src + slab * (size_t)(R * Cc);
    float* d = dst + slab * (size_t)(R * Cc);
    const int c0 = blockIdx.x * 32;
    const int r0 = blockIdx.y * 32;

    #pragma unroll
    for (int i = 0; i < 32; i += 8) {
        int r = r0 + threadIdx.y + i;
        int c = c0 + threadIdx.x;
        if (r < R && c < Cc) tile[threadIdx.y + i][threadIdx.x] = s[(size_t)r * Cc + c];
    }
    __syncthreads();
    #pragma unroll
    for (int i = 0; i < 32; i += 8) {
        int c = c0 + threadIdx.y + i;
        int r = r0 + threadIdx.x;
        if (r < R && c < Cc) d[(size_t)c * R + r] = tile[threadIdx.x][threadIdx.y + i];
    }
}

extern "C" void kernel_launch(void* const* d_in, const int* in_sizes, int n_in,
                              void* d_out, int out_size) {
    const float* x  = (const float*)d_in[0];
    const float* wd = (const float*)d_in[1];
    const float* wu = (const float*)d_in[2];
    const float* wr = (const float*)d_in[3];
    const float* wl = (const float*)d_in[4];
    float* out = (float*)d_out;

    float* tbuf = nullptr;
    cudaGetSymbolAddress((void**)&tbuf, g_tbuf);

    // W pass: 640 threads, 5 j's/thread; H pass: 384 threads, 3 j's/thread
    constexpr int SMEM_W = (TCO * WSTR + C_ * (W_ + 8)) * 4;  // 180,260 B
    constexpr int SMEM_H = (TCO * WSTR + C_ * (H_ + 8)) * 4;  // 114,724 B
    static bool attr_done = false;
    if (!attr_done) {
        cudaFuncSetAttribute((const void*)pass_kernel<W_, 5, 640>,
                             cudaFuncAttributeMaxDynamicSharedMemorySize, SMEM_W);
        cudaFuncSetAttribute((const void*)pass_kernel<H_, 3, 384>,
                             cudaFuncAttributeMaxDynamicSharedMemorySize, SMEM_H);
        attr_done = true;
    }

    // working copy of x (scan runs in-place on out)
    cudaMemcpyAsync(out, x, TOTAL * sizeof(float), cudaMemcpyDeviceToDevice);

    const dim3 grid(NCTA, B_, 1);

    // down + up: conv along W (contiguous), scan over H rows
    pass_kernel<W_, 5, 640><<<grid, 640, SMEM_W>>>(out, wd, wu, H_);

    // transpose (B,C,H,W) -> (B,C,W,H)
    const dim3 tb(32, 8);
    const dim3 tg1((W_ + 31) / 32, (H_ + 31) / 32, B_ * C_);
    transpose_kernel<<<tg1, tb>>>(out, tbuf, H_, W_);

    // right + left: conv along H (now contiguous), scan over W rows
    pass_kernel<H_, 3, 384><<<grid, 384, SMEM_H>>>(tbuf, wr, wl, W_);

    // transpose back
    const dim3 tg2((H_ + 31) / 32, (W_ + 31) / 32, B_ * C_);
    transpose_kernel<<<tg2, tb>>>(tbuf, out, W_, H_);
}

// round 7
// speedup vs baseline: 3.7864x; 3.6696x over previous
#include <cuda_runtime.h>
#include <cstdint>

using u64 = unsigned long long;

// Problem constants
constexpr int B_ = 16, C_ = 128, H_ = 72, W_ = 200, K_ = 9;
constexpr int CS = H_ * W_;
constexpr size_t BS = (size_t)C_ * CS;
constexpr size_t TOTAL = (size_t)B_ * BS;
constexpr int NCIP = C_ / 2;             // 64 ci-pairs
constexpr int WCO = NCIP * K_;           // 576 u64 per c_out
constexpr int WST = WCO + 2;             // 578: rows 16B-aligned, co's 4 banks apart

// Scratch: transposed layout + ci-paired weights (4 directions)
__device__ float g_tbuf[TOTAL];
__device__ __align__(16) u64 g_wp[4 * C_ * WCO];

__device__ __forceinline__ void fma2(u64& d, u64 a, u64 b) {
    asm("fma.rn.f32x2 %0, %1, %2, %0;" : "+l"(d) : "l"(a), "l"(b));
}
__device__ __forceinline__ u64 pack2(float a, float b) {
    u64 r; asm("mov.b64 %0, {%1, %2};" : "=l"(r) : "f"(a), "f"(b)); return r;
}
__device__ __forceinline__ float hsum2(u64 v) {
    float x, y; asm("mov.b64 {%0, %1}, %2;" : "=f"(x), "=f"(y) : "l"(v));
    return x + y;
}
__device__ __forceinline__ void cp_async16(uint32_t saddr, const void* g) {
    asm volatile("cp.async.cg.shared.global [%0], [%1], 16;" :: "r"(saddr), "l"(g));
}
__device__ __forceinline__ void cp_async_wait_all() {
    asm volatile("cp.async.commit_group;\n\tcp.async.wait_group 0;" ::: "memory");
}

// Pre-pair weights over ci: g_wp[dir][co][cip*9+k] = (w[co][2cip][k], w[co][2cip+1][k])
__global__ void prep_weights(const float* w0, const float* w1,
                             const float* w2, const float* w3) {
    const float* ws[4] = {w0, w1, w2, w3};
    const int tot = C_ * WCO;
    for (int i = blockIdx.x * blockDim.x + threadIdx.x; i < 4 * tot;
         i += gridDim.x * blockDim.x) {
        int d = i / tot, r = i % tot;
        int co = r / WCO, rr = r % WCO;
        int cip = rr / K_, k = rr % K_;
        const float* w = ws[d];
        g_wp[i] = pack2(w[(size_t)co * C_ * K_ + (2 * cip) * K_ + k],
                        w[(size_t)co * C_ * K_ + (2 * cip + 1) * K_ + k]);
    }
}

// One scan step: cur[b,co,j] += relu( sum_{ci,k} w[co,ci,k] * prev[b,ci,j+k-4] )
// ci paired into f32x2 lanes.
template <int L, int TJ, int TCO, int JT, int NT>
__global__ void __launch_bounds__(NT, 1)
step_kernel(float* __restrict__ base, const u64* __restrict__ wp,
            int prevIdx, int curIdx) {
    constexpr int QW = TJ + 8;           // p2 window (4-halo each side)
    constexpr int NJG = TJ / JT;
    extern __shared__ __align__(16) u64 sm[];
    u64* w_s = sm;                       // [TCO][WST]
    u64* p_s = sm + TCO * WST;           // [NCIP][QW]

    const int t = threadIdx.x;
    const int jbase = blockIdx.x * TJ;
    const int cobase = blockIdx.y * TCO;
    const int b = blockIdx.z;
    float* __restrict__ bb = base + (size_t)b * BS;
    const float* __restrict__ prow = bb + (size_t)prevIdx * L;
    float* __restrict__ crow = bb + (size_t)curIdx * L;

    const int cog = t / NJG;             // c_out (1 per thread)
    const int jg = t % NJG;
    const int j0 = jg * JT;
    const int gco = cobase + cog;

    // ---- stage weights via cp.async 16B (TCO*WCO/2 chunks) ----
    {
        const u64* wg = wp + (size_t)cobase * WCO;
        const uint32_t wbase = (uint32_t)__cvta_generic_to_shared(w_s);
        constexpr int NCH = TCO * WCO / 2;   // 16B chunks
        #pragma unroll
        for (int i = t; i < NCH; i += NT) {
            int co = i / (WCO / 2), r = i % (WCO / 2);
            cp_async16(wbase + (uint32_t)(co * WST + 2 * r) * 8u,
                       wg + (size_t)co * WCO + 2 * r);
        }
    }
    // ---- stage prev row as ci-pairs with zero halo (overlaps with cp.async) ----
    for (int i = t; i < NCIP * QW; i += NT) {
        int cip = i / QW, q = i % QW;
        int gj = jbase + q - 4;
        float a = 0.f, c = 0.f;
        if (gj >= 0 && gj < L) {
            a = prow[(size_t)(2 * cip) * CS + gj];
            c = prow[(size_t)(2 * cip + 1) * CS + gj];
        }
        p_s[i] = pack2(a, c);
    }
    // ---- prefetch this thread's cur-row base values ----
    float xv[JT];
    #pragma unroll
    for (int n = 0; n < JT; ++n)
        xv[n] = crow[(size_t)gco * CS + jbase + j0 + n];

    cp_async_wait_all();
    __syncthreads();

    u64 acc[JT];
    #pragma unroll
    for (int n = 0; n < JT; ++n) acc[n] = 0ull;

    const u64* pw = p_s + j0;
    const u64* wc = w_s + cog * WST;

    #pragma unroll 2
    for (int cip = 0; cip < NCIP; ++cip) {
        u64 win[JT + 8];
        #pragma unroll
        for (int q = 0; q < JT + 8; ++q) win[q] = pw[q];
        #pragma unroll
        for (int k = 0; k < K_; ++k) {
            const u64 wk = wc[cip * K_ + k];
            #pragma unroll
            for (int n = 0; n < JT; ++n) fma2(acc[n], wk, win[k + n]);
        }
        pw += QW;
    }

    #pragma unroll
    for (int n = 0; n < JT; ++n)
        crow[(size_t)gco * CS + jbase + j0 + n] = xv[n] + fmaxf(hsum2(acc[n]), 0.f);
}

// Transpose per (b,c) slab: src slab R x Cc (row-major) -> dst slab Cc x R.
__global__ void transpose_kernel(const float* __restrict__ src, float* __restrict__ dst,
                                 int R, int Cc) {
    __shared__ float tile[32][33];
    const size_t slab = blockIdx.z;
    const float* s = src + slab * (size_t)(R * Cc);
    float* d = dst + slab * (size_t)(R * Cc);
    const int c0 = blockIdx.x * 32;
    const int r0 = blockIdx.y * 32;

    #pragma unroll
    for (int i = 0; i < 32; i += 8) {
        int r = r0 + threadIdx.y + i, c = c0 + threadIdx.x;
        if (r < R && c < Cc) tile[threadIdx.y + i][threadIdx.x] = s[(size_t)r * Cc + c];
    }
    __syncthreads();
    #pragma unroll
    for (int i = 0; i < 32; i += 8) {
        int c = c0 + threadIdx.y + i, r = r0 + threadIdx.x;
        if (r < R && c < Cc) d[(size_t)c * R + r] = tile[threadIdx.x][threadIdx.y + i];
    }
}

// W pass: TJ=200, TCO=16, JT=10, NT=320, grid (1,8,16); smem 180,480 B
// H pass: TJ=72,  TCO=16, JT=9,  NT=128, grid (1,8,16); smem 114,944 B
constexpr int SMEM_W = (16 * WST + NCIP * (W_ + 8)) * 8;
constexpr int SMEM_H = (16 * WST + NCIP * (H_ + 8)) * 8;
static_assert(SMEM_W <= 227 * 1024, "smem W over limit");
static_assert(SMEM_H <= 227 * 1024, "smem H over limit");

extern "C" void kernel_launch(void* const* d_in, const int* in_sizes, int n_in,
                              void* d_out, int out_size) {
    const float* x  = (const float*)d_in[0];
    const float* wd = (const float*)d_in[1];
    const float* wu = (const float*)d_in[2];
    const float* wr = (const float*)d_in[3];
    const float* wl = (const float*)d_in[4];
    float* out = (float*)d_out;

    // one-time setup: runs on the (uncaptured) correctness call only
    static float* tbuf = nullptr;
    static u64* wp = nullptr;
    static bool init_done = false;
    if (!init_done) {
        cudaGetSymbolAddress((void**)&tbuf, g_tbuf);
        cudaGetSymbolAddress((void**)&wp, g_wp);
        cudaFuncSetAttribute((const void*)step_kernel<W_, 200, 16, 10, 320>,
                             cudaFuncAttributeMaxDynamicSharedMemorySize, SMEM_W);
        cudaFuncSetAttribute((const void*)step_kernel<H_, 72, 16, 9, 128>,
                             cudaFuncAttributeMaxDynamicSharedMemorySize, SMEM_H);
        init_done = true;
    }

    // pre-pair weights (reads inputs every call -> deterministic)
    prep_weights<<<256, 256>>>(wd, wu, wr, wl);

    // working copy of x (scan runs in-place on out)
    cudaMemcpyAsync(out, x, TOTAL * sizeof(float), cudaMemcpyDeviceToDevice);

    const u64* wpd = wp + 0 * (size_t)C_ * WCO;
    const u64* wpu = wp + 1 * (size_t)C_ * WCO;
    const u64* wpr = wp + 2 * (size_t)C_ * WCO;
    const u64* wpl = wp + 3 * (size_t)C_ * WCO;

    // ---- down / up: conv along W (contiguous), scan over H ----
    const dim3 gw(1, 8, 16);
    for (int h = 1; h < H_; ++h)
        step_kernel<W_, 200, 16, 10, 320><<<gw, 320, SMEM_W>>>(out, wpd, h - 1, h);
    for (int h = H_ - 2; h >= 0; --h)
        step_kernel<W_, 200, 16, 10, 320><<<gw, 320, SMEM_W>>>(out, wpu, h + 1, h);

    // ---- transpose (B,C,H,W) -> (B,C,W,H) ----
    const dim3 tb(32, 8);
    const dim3 tg1((W_ + 31) / 32, (H_ + 31) / 32, B_ * C_);
    transpose_kernel<<<tg1, tb>>>(out, tbuf, H_, W_);

    // ---- right / left: conv along H (now contiguous), scan over W ----
    const dim3 gh(1, 8, 16);
    for (int w = 1; w < W_; ++w)
        step_kernel<H_, 72, 16, 9, 128><<<gh, 128, SMEM_H>>>(tbuf, wpr, w - 1, w);
    for (int w = W_ - 2; w >= 0; --w)
        step_kernel<H_, 72, 16, 9, 128><<<gh, 128, SMEM_H>>>(tbuf, wpl, w + 1, w);

    // ---- transpose back ----
    const dim3 tg2((H_ + 31) / 32, (W_ + 31) / 32, B_ * C_);
    transpose_kernel<<<tg2, tb>>>(tbuf, out, W_, H_);
}